// round 7
// baseline (speedup 1.0000x reference)
#include <cuda_runtime.h>

#define NN   50000
#define NHE  10000
#define NE   800000
#define NI   800000
#define HID  128
#define OUTC 64

// ---------------- device scratch (no allocations; referenced only in device code) ----------------
__device__ __align__(16) float g_A[NN * HID];    // theta-product / edge agg
__device__ __align__(16) float g_B[NN * HID];    // lin-product / agg@wrel
__device__ __align__(16) float g_X1[NN * HID];
__device__ __align__(16) float g_X2[NN * HID];
__device__ __align__(16) float g_M[NHE * HID];   // hyperedge features
__device__ __align__(16) float g_Wc[HID * HID];  // combined root+lin weight
__device__ __align__(16) float g_bsum[HID];      // combined bias
__device__ float g_Binv[NHE];
__device__ float g_Dinv[NN];

__device__ int g_idx64;          // 1 if index tensors are int64, 0 if int32
__device__ int g_deg_he[NHE];
__device__ int g_off_he[NHE + 1];
__device__ int g_cur_he[NHE];
__device__ int g_deg_nh[NN];
__device__ int g_off_nh[NN + 1];
__device__ int g_cur_nh[NN];
__device__ int g_deg_nd[NN];
__device__ int g_off_nd[NN + 1];
__device__ int g_cur_nd[NN];
__device__ int g_list_he[NI];   // nodes per hyperedge
__device__ int g_list_nh[NI];   // hyperedges per node
__device__ int g_list_nd[NE];   // srcs per dst node

__device__ __forceinline__ float leakyf(float x) { return x >= 0.f ? x : 0.01f * x; }
__device__ __forceinline__ int clampi(int v, int hi) { return v < 0 ? 0 : (v >= hi ? hi - 1 : v); }

__device__ __forceinline__ int idxat(const int* __restrict__ a, int pos) {
    return g_idx64 ? a[2 * (long long)pos] : a[pos];
}

__device__ __forceinline__ const float* srcbuf(int id, const float* ext) {
    switch (id) {
        case 0: return g_A;
        case 1: return g_B;
        case 2: return g_X1;
        case 3: return g_X2;
        default: return ext;
    }
}
__device__ __forceinline__ float* dstbuf(int id, float* ext) {
    switch (id) {
        case 0: return g_A;
        case 1: return g_B;
        case 2: return g_X1;
        case 3: return g_X2;
        default: return ext;
    }
}

// ---------------- index dtype detect ----------------
__global__ void detect_kernel(const int* __restrict__ he) {
    __shared__ int any;
    if (threadIdx.x == 0) any = 0;
    __syncthreads();
    if (he[2 * threadIdx.x + 1] != 0) atomicOr(&any, 1);
    __syncthreads();
    if (threadIdx.x == 0) g_idx64 = (any == 0) ? 1 : 0;
}

// ---------------- CSR build ----------------
__global__ void zero_deg_kernel() {
    int i = blockIdx.x * blockDim.x + threadIdx.x;
    if (i < NHE) g_deg_he[i] = 0;
    if (i < NN) { g_deg_nh[i] = 0; g_deg_nd[i] = 0; }
}

__global__ void count_kernel(const int* __restrict__ he, const int* __restrict__ ed) {
    int i = blockIdx.x * blockDim.x + threadIdx.x;
    if (i < NI) {
        atomicAdd(&g_deg_nh[clampi(idxat(he, i), NN)], 1);
        atomicAdd(&g_deg_he[clampi(idxat(he, NI + i), NHE)], 1);
    }
    if (i < NE) {
        atomicAdd(&g_deg_nd[clampi(idxat(ed, NE + i), NN)], 1);
    }
}

// 3 independent scans in one launch: blockIdx.x = which (0=he, 1=node-hyper, 2=node-dst)
__global__ void scan_kernel() {
    int which = blockIdx.x;
    const int* deg; int n; int* off; int* cur; float* inv;
    if (which == 0)      { deg = g_deg_he; n = NHE; off = g_off_he; cur = g_cur_he; inv = g_Binv; }
    else if (which == 1) { deg = g_deg_nh; n = NN;  off = g_off_nh; cur = g_cur_nh; inv = g_Dinv; }
    else                 { deg = g_deg_nd; n = NN;  off = g_off_nd; cur = g_cur_nd; inv = 0; }

    __shared__ int sh[1024];
    int tid = threadIdx.x;
    int chunk = (n + 1023) / 1024;
    int lo = tid * chunk;
    int hi = lo + chunk; if (hi > n) hi = n; if (lo > n) lo = n;
    int s = 0;
    for (int i = lo; i < hi; ++i) s += deg[i];
    sh[tid] = s;
    __syncthreads();
    for (int d = 1; d < 1024; d <<= 1) {
        int v = (tid >= d) ? sh[tid - d] : 0;
        __syncthreads();
        sh[tid] += v;
        __syncthreads();
    }
    int run = sh[tid] - s;  // exclusive prefix at chunk start
    for (int i = lo; i < hi; ++i) {
        int d = deg[i];
        off[i] = run; cur[i] = run;
        if (inv) inv[i] = d ? 1.0f / (float)d : 0.0f;
        run += d;
    }
    if (tid == 1023) off[n] = sh[1023];
}

__global__ void fill_kernel(const int* __restrict__ he, const int* __restrict__ ed) {
    int i = blockIdx.x * blockDim.x + threadIdx.x;
    if (i < NI) {
        int n = clampi(idxat(he, i), NN);
        int h = clampi(idxat(he, NI + i), NHE);
        g_list_he[atomicAdd(&g_cur_he[h], 1)] = n;
        g_list_nh[atomicAdd(&g_cur_nh[n], 1)] = h;
    }
    if (i < NE) {
        int s = clampi(idxat(ed, i), NN);
        int d = clampi(idxat(ed, NE + i), NN);
        g_list_nd[atomicAdd(&g_cur_nd[d], 1)] = s;
    }
}

// ---------------- gather segment-sums (1 warp per output row) ----------------
__global__ void gather_he_kernel() {
    int row = (blockIdx.x * blockDim.x + threadIdx.x) >> 5;
    if (row >= NHE) return;
    int lane = threadIdx.x & 31;
    int beg = g_off_he[row], end = g_off_he[row + 1];
    const float4* src = (const float4*)g_A;
    float ax = 0.f, ay = 0.f, az = 0.f, aw = 0.f;
    int i = beg;
    for (; i + 4 <= end; i += 4) {
        int n0 = g_list_he[i], n1 = g_list_he[i + 1], n2 = g_list_he[i + 2], n3 = g_list_he[i + 3];
        float4 v0 = src[n0 * 32 + lane];
        float4 v1 = src[n1 * 32 + lane];
        float4 v2 = src[n2 * 32 + lane];
        float4 v3 = src[n3 * 32 + lane];
        ax += (v0.x + v1.x) + (v2.x + v3.x);
        ay += (v0.y + v1.y) + (v2.y + v3.y);
        az += (v0.z + v1.z) + (v2.z + v3.z);
        aw += (v0.w + v1.w) + (v2.w + v3.w);
    }
    for (; i < end; ++i) {
        int n = g_list_he[i];
        float4 v = src[n * 32 + lane];
        ax += v.x; ay += v.y; az += v.z; aw += v.w;
    }
    float b = g_Binv[row];
    ((float4*)g_M)[row * 32 + lane] = make_float4(ax * b, ay * b, az * b, aw * b);
}

__global__ void gather_node_fuse_kernel(const float4* __restrict__ hcb,
                                        const float4* __restrict__ linb,
                                        int outsel) {
    int row = (blockIdx.x * blockDim.x + threadIdx.x) >> 5;
    if (row >= NN) return;
    int lane = threadIdx.x & 31;
    int beg = g_off_nh[row], end = g_off_nh[row + 1];
    const float4* m = (const float4*)g_M;
    float ax = 0.f, ay = 0.f, az = 0.f, aw = 0.f;
    int i = beg;
    for (; i + 4 <= end; i += 4) {
        int h0 = g_list_nh[i], h1 = g_list_nh[i + 1], h2 = g_list_nh[i + 2], h3 = g_list_nh[i + 3];
        float4 v0 = m[h0 * 32 + lane];
        float4 v1 = m[h1 * 32 + lane];
        float4 v2 = m[h2 * 32 + lane];
        float4 v3 = m[h3 * 32 + lane];
        ax += (v0.x + v1.x) + (v2.x + v3.x);
        ay += (v0.y + v1.y) + (v2.y + v3.y);
        az += (v0.z + v1.z) + (v2.z + v3.z);
        aw += (v0.w + v1.w) + (v2.w + v3.w);
    }
    for (; i < end; ++i) {
        int h = g_list_nh[i];
        float4 v = m[h * 32 + lane];
        ax += v.x; ay += v.y; az += v.z; aw += v.w;
    }
    float dinv = g_Dinv[row];
    float4 b1 = hcb[lane];
    float4 b2 = linb[lane];
    const float4* linP = (const float4*)g_B;
    float4 l = linP[row * 32 + lane];
    float4 r;
    r.x = leakyf(ax * dinv + b1.x + b2.x + l.x);
    r.y = leakyf(ay * dinv + b1.y + b2.y + l.y);
    r.z = leakyf(az * dinv + b1.z + b2.z + l.z);
    r.w = leakyf(aw * dinv + b1.w + b2.w + l.w);
    ((float4*)dstbuf(outsel, 0))[row * 32 + lane] = r;
}

__global__ void gather_edge_kernel(int srcsel) {
    int row = (blockIdx.x * blockDim.x + threadIdx.x) >> 5;
    if (row >= NN) return;
    int lane = threadIdx.x & 31;
    int beg = g_off_nd[row], end = g_off_nd[row + 1];
    const float4* src = (const float4*)srcbuf(srcsel, 0);
    float ax = 0.f, ay = 0.f, az = 0.f, aw = 0.f;
    int i = beg;
    for (; i + 4 <= end; i += 4) {
        int n0 = g_list_nd[i], n1 = g_list_nd[i + 1], n2 = g_list_nd[i + 2], n3 = g_list_nd[i + 3];
        float4 v0 = src[n0 * 32 + lane];
        float4 v1 = src[n1 * 32 + lane];
        float4 v2 = src[n2 * 32 + lane];
        float4 v3 = src[n3 * 32 + lane];
        ax += (v0.x + v1.x) + (v2.x + v3.x);
        ay += (v0.y + v1.y) + (v2.y + v3.y);
        az += (v0.z + v1.z) + (v2.z + v3.z);
        aw += (v0.w + v1.w) + (v2.w + v3.w);
    }
    for (; i < end; ++i) {
        int n = g_list_nd[i];
        float4 v = src[n * 32 + lane];
        ax += v.x; ay += v.y; az += v.z; aw += v.w;
    }
    ((float4*)g_A)[row * 32 + lane] = make_float4(ax, ay, az, aw);
}

__global__ void combine_kernel(const float* __restrict__ a, const float* __restrict__ b,
                               const float* __restrict__ ba, const float* __restrict__ bb) {
    int i = blockIdx.x * blockDim.x + threadIdx.x;
    if (i < HID * HID) g_Wc[i] = a[i] + b[i];
    if (i < HID) g_bsum[i] = ba[i] + bb[i];
}

// ---------------- fp32 SGEMM: C[M x Kout] = A[M x 128] @ W[128 x Kout] ----------------
// 128x128 block tile, BK=16, 256 threads, 8x8 per thread, smem double buffered.
// MODE 0: C = acc ; MODE 1: C = acc + bias_ext ; MODE 2: C = leaky(acc + g_B + g_bsum)
template <int MODE>
__global__ __launch_bounds__(256, 2)
void gemm128_kernel(const float* __restrict__ Aext, const float* __restrict__ Wext,
                    float* __restrict__ Cext, const float* __restrict__ bias_ext,
                    int asel, int csel, int wsel, int M, int Kout) {
    const float* A = srcbuf(asel, Aext);
    const float* W = (wsel == 1) ? g_Wc : Wext;
    float* C = dstbuf(csel, Cext);

    __shared__ float As[2][16][128];   // [buf][k][m]
    __shared__ float Bs[2][16][128];   // [buf][k][n]

    int tid = threadIdx.x;
    int tx = tid & 15;     // col group: cols tx*8 .. tx*8+7
    int ty = tid >> 4;     // row group: rows ty*8 .. ty*8+7
    int brow = blockIdx.x * 128;

    // A-load mapping: each thread loads A[brow+lm][ks+lk .. ks+lk+7] (2 float4)
    int lm = tid >> 1;
    int lk = (tid & 1) * 8;
    // B-load mapping: each thread loads W[ks+bkk][bn0 .. bn0+7] (2 float4)
    int bkk = tid >> 4;
    int bn0 = (tid & 15) * 8;

    const float4 f4z = make_float4(0.f, 0.f, 0.f, 0.f);

    float acc[8][8];
#pragma unroll
    for (int i = 0; i < 8; ++i)
#pragma unroll
        for (int j = 0; j < 8; ++j) acc[i][j] = 0.f;

    int aRow = brow + lm;
    bool aOk = (aRow < M);
    const float* aBase = &A[(size_t)(aOk ? aRow : 0) * 128];

    // ---- preload stage 0 ----
    float4 pa0, pa1, pb0, pb1;
    {
        pa0 = aOk ? *(const float4*)&aBase[lk]     : f4z;
        pa1 = aOk ? *(const float4*)&aBase[lk + 4] : f4z;
        const float* wrow = &W[bkk * Kout];
        pb0 = (bn0 < Kout) ? *(const float4*)&wrow[bn0]     : f4z;
        pb1 = (bn0 < Kout) ? *(const float4*)&wrow[bn0 + 4] : f4z;
    }
    // store stage 0
    As[0][lk + 0][lm] = pa0.x; As[0][lk + 1][lm] = pa0.y;
    As[0][lk + 2][lm] = pa0.z; As[0][lk + 3][lm] = pa0.w;
    As[0][lk + 4][lm] = pa1.x; As[0][lk + 5][lm] = pa1.y;
    As[0][lk + 6][lm] = pa1.z; As[0][lk + 7][lm] = pa1.w;
    *(float4*)&Bs[0][bkk][bn0] = pb0;
    *(float4*)&Bs[0][bkk][bn0 + 4] = pb1;
    __syncthreads();

    int cur = 0;
#pragma unroll
    for (int s = 0; s < 8; ++s) {
        // prefetch next stage to registers
        if (s < 7) {
            int ks = (s + 1) * 16;
            pa0 = aOk ? *(const float4*)&aBase[ks + lk]     : f4z;
            pa1 = aOk ? *(const float4*)&aBase[ks + lk + 4] : f4z;
            const float* wrow = &W[(ks + bkk) * Kout];
            pb0 = (bn0 < Kout) ? *(const float4*)&wrow[bn0]     : f4z;
            pb1 = (bn0 < Kout) ? *(const float4*)&wrow[bn0 + 4] : f4z;
        }
        // compute current stage
#pragma unroll
        for (int k = 0; k < 16; ++k) {
            float4 a0 = *(const float4*)&As[cur][k][ty * 8];
            float4 a1 = *(const float4*)&As[cur][k][ty * 8 + 4];
            float4 b0 = *(const float4*)&Bs[cur][k][tx * 8];
            float4 b1 = *(const float4*)&Bs[cur][k][tx * 8 + 4];
            float ar[8] = {a0.x, a0.y, a0.z, a0.w, a1.x, a1.y, a1.z, a1.w};
            float br[8] = {b0.x, b0.y, b0.z, b0.w, b1.x, b1.y, b1.z, b1.w};
#pragma unroll
            for (int i = 0; i < 8; ++i)
#pragma unroll
                for (int j = 0; j < 8; ++j) acc[i][j] += ar[i] * br[j];
        }
        // commit next stage
        if (s < 7) {
            int nxt = cur ^ 1;
            As[nxt][lk + 0][lm] = pa0.x; As[nxt][lk + 1][lm] = pa0.y;
            As[nxt][lk + 2][lm] = pa0.z; As[nxt][lk + 3][lm] = pa0.w;
            As[nxt][lk + 4][lm] = pa1.x; As[nxt][lk + 5][lm] = pa1.y;
            As[nxt][lk + 6][lm] = pa1.z; As[nxt][lk + 7][lm] = pa1.w;
            *(float4*)&Bs[nxt][bkk][bn0] = pb0;
            *(float4*)&Bs[nxt][bkk][bn0 + 4] = pb1;
            __syncthreads();
            cur = nxt;
        }
    }

    // ---- epilogue ----
    if (tx * 8 >= Kout) return;  // Kout=64: right half idle
#pragma unroll
    for (int i = 0; i < 8; ++i) {
        int gr = brow + ty * 8 + i;
        if (gr >= M) continue;
        float out[8];
#pragma unroll
        for (int j = 0; j < 8; ++j) {
            int gc = tx * 8 + j;
            float v = acc[i][j];
            if (MODE == 1) v += bias_ext[gc];
            if (MODE == 2) v = leakyf(v + g_B[gr * 128 + gc] + g_bsum[gc]);
            out[j] = v;
        }
        float* crow = &C[(size_t)gr * Kout + tx * 8];
        *(float4*)&crow[0] = make_float4(out[0], out[1], out[2], out[3]);
        *(float4*)&crow[4] = make_float4(out[4], out[5], out[6], out[7]);
    }
}

// ---------------- launch ----------------
extern "C" void kernel_launch(void* const* d_in, const int* in_sizes, int n_in,
                              void* d_out, int out_size) {
    const float* X     = (const float*)d_in[0];
    const int* eidx    = (const int*)d_in[1];   // int32 or int64 (auto-detected)
    const int* hidx    = (const int*)d_in[2];
    const float* hc1w  = (const float*)d_in[3];
    const float* hc1b  = (const float*)d_in[4];
    const float* lin1w = (const float*)d_in[5];
    const float* lin1b = (const float*)d_in[6];
    const float* hc2w  = (const float*)d_in[7];
    const float* hc2b  = (const float*)d_in[8];
    const float* lin2w = (const float*)d_in[9];
    const float* lin2b = (const float*)d_in[10];
    const float* c1wrel  = (const float*)d_in[11];
    const float* c1brel  = (const float*)d_in[12];
    const float* c1wroot = (const float*)d_in[13];
    const float* glin1w  = (const float*)d_in[14];
    const float* glin1b  = (const float*)d_in[15];
    const float* c2wrel  = (const float*)d_in[16];
    const float* c2brel  = (const float*)d_in[17];
    const float* c2wroot = (const float*)d_in[18];
    const float* glin2w  = (const float*)d_in[19];
    const float* glin2b  = (const float*)d_in[20];
    const float* fcw = (const float*)d_in[21];
    const float* fcb = (const float*)d_in[22];

    const size_t NX = (size_t)NN * HID;
    const size_t NYsz = (size_t)NN * OUTC;
    bool full_out = ((size_t)out_size >= NX + NYsz);
    float* outX = (float*)d_out;
    float* outY = full_out ? (outX + NX) : (float*)d_out;
    int final_csel = full_out ? -1 : 3;
    int fc_asel    = full_out ? -1 : 3;
    const float* fc_Aext = full_out ? outX : (const float*)0;

    const int TPB = 256;
    int gG = (NN + 127) / 128;                 // gemm blocks
    int gbE   = (NE + TPB - 1) / TPB;
    int gbHEw = (NHE * 32 + TPB - 1) / TPB;
    int gbNw  = (NN * 32 + TPB - 1) / TPB;

    // ---- dtype detect + CSR build ----
    detect_kernel<<<1, 256>>>(hidx);
    zero_deg_kernel<<<(NN + TPB - 1) / TPB, TPB>>>();
    count_kernel<<<gbE, TPB>>>(hidx, eidx);
    scan_kernel<<<3, 1024>>>();
    fill_kernel<<<gbE, TPB>>>(hidx, eidx);

    // ---- layer 1 (hypergraph) ----
    gemm128_kernel<0><<<gG, TPB>>>(X, hc1w, 0, 0, -1, 0, 0, NN, 128);   // g_A = X @ hc1w
    gemm128_kernel<0><<<gG, TPB>>>(X, lin1w, 0, 0, -1, 1, 0, NN, 128);  // g_B = X @ lin1w
    gather_he_kernel<<<gbHEw, TPB>>>();
    gather_node_fuse_kernel<<<gbNw, TPB>>>((const float4*)hc1b, (const float4*)lin1b, 2);  // -> g_X1

    // ---- layer 2 (hypergraph) ----
    gemm128_kernel<0><<<gG, TPB>>>(0, hc2w, 0, 0, 2, 0, 0, NN, 128);    // g_A = g_X1 @ hc2w
    gemm128_kernel<0><<<gG, TPB>>>(0, lin2w, 0, 0, 2, 1, 0, NN, 128);   // g_B = g_X1 @ lin2w
    gather_he_kernel<<<gbHEw, TPB>>>();
    gather_node_fuse_kernel<<<gbNw, TPB>>>((const float4*)hc2b, (const float4*)lin2b, 3);  // -> g_X2

    // ---- layer 3 (graph) ----
    combine_kernel<<<(HID * HID + TPB - 1) / TPB, TPB>>>(c1wroot, glin1w, c1brel, glin1b);
    gather_edge_kernel<<<gbNw, TPB>>>(3);                               // g_A = segsum(g_X2)
    gemm128_kernel<0><<<gG, TPB>>>(0, c1wrel, 0, 0, 0, 1, 0, NN, 128);  // g_B = g_A @ c1wrel
    gemm128_kernel<2><<<gG, TPB>>>(0, 0, 0, 0, 3, 2, 1, NN, 128);       // g_X1 = leaky(g_X2@Wc + g_B + bsum)

    // ---- layer 4 (graph) ----
    combine_kernel<<<(HID * HID + TPB - 1) / TPB, TPB>>>(c2wroot, glin2w, c2brel, glin2b);
    gather_edge_kernel<<<gbNw, TPB>>>(2);                               // g_A = segsum(g_X1)
    gemm128_kernel<0><<<gG, TPB>>>(0, c2wrel, 0, 0, 0, 1, 0, NN, 128);  // g_B = g_A @ c2wrel
    gemm128_kernel<2><<<gG, TPB>>>(0, 0, outX, 0, 2, final_csel, 1, NN, 128);  // X4

    // ---- fc head ----
    gemm128_kernel<1><<<gG, TPB>>>(fc_Aext, fcw, outY, fcb, fc_asel, -1, 0, NN, 64);
}

// round 8
// speedup vs baseline: 1.5834x; 1.5834x over previous
#include <cuda_runtime.h>

#define NN   50000
#define NHE  10000
#define NE   800000
#define NI   800000
#define HID  128
#define OUTC 64

// ---------------- device scratch (no allocations; referenced only in device code) ----------------
__device__ __align__(16) float g_A[NN * HID];    // theta-product / edge agg
__device__ __align__(16) float g_B[NN * HID];    // lin-product / agg@wrel
__device__ __align__(16) float g_X1[NN * HID];
__device__ __align__(16) float g_X2[NN * HID];
__device__ __align__(16) float g_M[NHE * HID];   // hyperedge features
__device__ __align__(16) float g_Wc[HID * HID];  // combined root+lin weight
__device__ __align__(16) float g_bsum[HID];      // combined bias
__device__ __align__(16) float g_Binv[NHE];
__device__ __align__(16) float g_Dinv[NN];

__device__ int g_idx64;          // 1 if index tensors are int64, 0 if int32
__device__ __align__(16) int g_deg_he[NHE];
__device__ __align__(16) int g_off_he[NHE + 1];
__device__ __align__(16) int g_cur_he[NHE];
__device__ __align__(16) int g_deg_nh[NN];
__device__ __align__(16) int g_off_nh[NN + 1];
__device__ __align__(16) int g_cur_nh[NN];
__device__ __align__(16) int g_deg_nd[NN];
__device__ __align__(16) int g_off_nd[NN + 1];
__device__ __align__(16) int g_cur_nd[NN];
__device__ int g_list_he[NI];   // nodes per hyperedge
__device__ int g_list_nh[NI];   // hyperedges per node
__device__ int g_list_nd[NE];   // srcs per dst node

__device__ __forceinline__ float leakyf(float x) { return x >= 0.f ? x : 0.01f * x; }
__device__ __forceinline__ int clampi(int v, int hi) { return v < 0 ? 0 : (v >= hi ? hi - 1 : v); }

__device__ __forceinline__ int idxat(const int* __restrict__ a, int pos) {
    return g_idx64 ? a[2 * (long long)pos] : a[pos];
}

__device__ __forceinline__ const float* srcbuf(int id, const float* ext) {
    switch (id) {
        case 0: return g_A;
        case 1: return g_B;
        case 2: return g_X1;
        case 3: return g_X2;
        default: return ext;
    }
}
__device__ __forceinline__ float* dstbuf(int id, float* ext) {
    switch (id) {
        case 0: return g_A;
        case 1: return g_B;
        case 2: return g_X1;
        case 3: return g_X2;
        default: return ext;
    }
}

// ---------------- index dtype detect ----------------
__global__ void detect_kernel(const int* __restrict__ he) {
    __shared__ int any;
    if (threadIdx.x == 0) any = 0;
    __syncthreads();
    if (he[2 * threadIdx.x + 1] != 0) atomicOr(&any, 1);
    __syncthreads();
    if (threadIdx.x == 0) g_idx64 = (any == 0) ? 1 : 0;
}

// ---------------- CSR build ----------------
__global__ void zero_deg_kernel() {
    int i = blockIdx.x * blockDim.x + threadIdx.x;
    if (i < NHE) g_deg_he[i] = 0;
    if (i < NN) { g_deg_nh[i] = 0; g_deg_nd[i] = 0; }
}

__global__ void count_kernel(const int* __restrict__ he, const int* __restrict__ ed) {
    int i = blockIdx.x * blockDim.x + threadIdx.x;
    if (i < NI) {
        atomicAdd(&g_deg_nh[clampi(idxat(he, i), NN)], 1);
        atomicAdd(&g_deg_he[clampi(idxat(he, NI + i), NHE)], 1);
    }
    if (i < NE) {
        atomicAdd(&g_deg_nd[clampi(idxat(ed, NE + i), NN)], 1);
    }
}

// ---------------- fast two-level shuffle scan ----------------
// 3 independent scans, blockIdx.x = which (0=he, 1=node-hyper, 2=node-dst).
// Coalesced int4 tile loads, warp shuffle inclusive scan, warp-sum scan, int4 stores.
__global__ void scan_kernel() {
    int which = blockIdx.x;
    const int* __restrict__ deg; int n; int* __restrict__ off; int* __restrict__ cur;
    float* __restrict__ inv;
    if (which == 0)      { deg = g_deg_he; n = NHE; off = g_off_he; cur = g_cur_he; inv = g_Binv; }
    else if (which == 1) { deg = g_deg_nh; n = NN;  off = g_off_nh; cur = g_cur_nh; inv = g_Dinv; }
    else                 { deg = g_deg_nd; n = NN;  off = g_off_nd; cur = g_cur_nd; inv = 0; }

    __shared__ int wsum[32];
    __shared__ int s_tot;
    __shared__ int s_run;
    int tid = threadIdx.x;
    int lane = tid & 31, wid = tid >> 5;
    if (tid == 0) s_run = 0;
    __syncthreads();

    int nt = (n + 4095) / 4096;
    for (int t = 0; t < nt; ++t) {
        int base = t * 4096 + tid * 4;
        int d0 = 0, d1 = 0, d2 = 0, d3 = 0;
        if (base + 3 < n) {
            int4 v = *(const int4*)&deg[base];
            d0 = v.x; d1 = v.y; d2 = v.z; d3 = v.w;
        } else {
            if (base + 0 < n) d0 = deg[base + 0];
            if (base + 1 < n) d1 = deg[base + 1];
            if (base + 2 < n) d2 = deg[base + 2];
            if (base + 3 < n) d3 = deg[base + 3];
        }
        int s = d0 + d1 + d2 + d3;
        int incl = s;
#pragma unroll
        for (int o = 1; o < 32; o <<= 1) {
            int v = __shfl_up_sync(0xFFFFFFFFu, incl, o);
            if (lane >= o) incl += v;
        }
        if (lane == 31) wsum[wid] = incl;
        __syncthreads();
        if (wid == 0) {
            int ws = wsum[lane];
            int wincl = ws;
#pragma unroll
            for (int o = 1; o < 32; o <<= 1) {
                int v = __shfl_up_sync(0xFFFFFFFFu, wincl, o);
                if (lane >= o) wincl += v;
            }
            wsum[lane] = wincl - ws;   // exclusive warp prefix
            if (lane == 31) s_tot = wincl;
        }
        __syncthreads();
        int excl = s_run + wsum[wid] + (incl - s);
        int o0 = excl, o1 = o0 + d0, o2 = o1 + d1, o3 = o2 + d2;
        if (base + 3 < n) {
            *(int4*)&off[base] = make_int4(o0, o1, o2, o3);
            *(int4*)&cur[base] = make_int4(o0, o1, o2, o3);
            if (inv) {
                float4 f;
                f.x = d0 ? 1.0f / (float)d0 : 0.0f;
                f.y = d1 ? 1.0f / (float)d1 : 0.0f;
                f.z = d2 ? 1.0f / (float)d2 : 0.0f;
                f.w = d3 ? 1.0f / (float)d3 : 0.0f;
                *(float4*)&inv[base] = f;
            }
        } else {
            if (base + 0 < n) { off[base + 0] = o0; cur[base + 0] = o0; if (inv) inv[base + 0] = d0 ? 1.0f / (float)d0 : 0.0f; }
            if (base + 1 < n) { off[base + 1] = o1; cur[base + 1] = o1; if (inv) inv[base + 1] = d1 ? 1.0f / (float)d1 : 0.0f; }
            if (base + 2 < n) { off[base + 2] = o2; cur[base + 2] = o2; if (inv) inv[base + 2] = d2 ? 1.0f / (float)d2 : 0.0f; }
            if (base + 3 < n) { off[base + 3] = o3; cur[base + 3] = o3; if (inv) inv[base + 3] = d3 ? 1.0f / (float)d3 : 0.0f; }
        }
        __syncthreads();
        if (tid == 0) s_run += s_tot;
        __syncthreads();
    }
    if (tid == 0) off[n] = s_run;
}

__global__ void fill_kernel(const int* __restrict__ he, const int* __restrict__ ed) {
    int i = blockIdx.x * blockDim.x + threadIdx.x;
    if (i < NI) {
        int n = clampi(idxat(he, i), NN);
        int h = clampi(idxat(he, NI + i), NHE);
        g_list_he[atomicAdd(&g_cur_he[h], 1)] = n;
        g_list_nh[atomicAdd(&g_cur_nh[n], 1)] = h;
    }
    if (i < NE) {
        int s = clampi(idxat(ed, i), NN);
        int d = clampi(idxat(ed, NE + i), NN);
        g_list_nd[atomicAdd(&g_cur_nd[d], 1)] = s;
    }
}

// ---------------- gather segment-sums (1 warp per output row) ----------------
__global__ void gather_he_kernel() {
    int row = (blockIdx.x * blockDim.x + threadIdx.x) >> 5;
    if (row >= NHE) return;
    int lane = threadIdx.x & 31;
    int beg = g_off_he[row], end = g_off_he[row + 1];
    const float4* src = (const float4*)g_A;
    float ax = 0.f, ay = 0.f, az = 0.f, aw = 0.f;
    int i = beg;
    for (; i + 4 <= end; i += 4) {
        int n0 = g_list_he[i], n1 = g_list_he[i + 1], n2 = g_list_he[i + 2], n3 = g_list_he[i + 3];
        float4 v0 = src[n0 * 32 + lane];
        float4 v1 = src[n1 * 32 + lane];
        float4 v2 = src[n2 * 32 + lane];
        float4 v3 = src[n3 * 32 + lane];
        ax += (v0.x + v1.x) + (v2.x + v3.x);
        ay += (v0.y + v1.y) + (v2.y + v3.y);
        az += (v0.z + v1.z) + (v2.z + v3.z);
        aw += (v0.w + v1.w) + (v2.w + v3.w);
    }
    for (; i < end; ++i) {
        int n = g_list_he[i];
        float4 v = src[n * 32 + lane];
        ax += v.x; ay += v.y; az += v.z; aw += v.w;
    }
    float b = g_Binv[row];
    ((float4*)g_M)[row * 32 + lane] = make_float4(ax * b, ay * b, az * b, aw * b);
}

__global__ void gather_node_fuse_kernel(const float4* __restrict__ hcb,
                                        const float4* __restrict__ linb,
                                        int outsel) {
    int row = (blockIdx.x * blockDim.x + threadIdx.x) >> 5;
    if (row >= NN) return;
    int lane = threadIdx.x & 31;
    int beg = g_off_nh[row], end = g_off_nh[row + 1];
    const float4* m = (const float4*)g_M;
    float ax = 0.f, ay = 0.f, az = 0.f, aw = 0.f;
    int i = beg;
    for (; i + 4 <= end; i += 4) {
        int h0 = g_list_nh[i], h1 = g_list_nh[i + 1], h2 = g_list_nh[i + 2], h3 = g_list_nh[i + 3];
        float4 v0 = m[h0 * 32 + lane];
        float4 v1 = m[h1 * 32 + lane];
        float4 v2 = m[h2 * 32 + lane];
        float4 v3 = m[h3 * 32 + lane];
        ax += (v0.x + v1.x) + (v2.x + v3.x);
        ay += (v0.y + v1.y) + (v2.y + v3.y);
        az += (v0.z + v1.z) + (v2.z + v3.z);
        aw += (v0.w + v1.w) + (v2.w + v3.w);
    }
    for (; i < end; ++i) {
        int h = g_list_nh[i];
        float4 v = m[h * 32 + lane];
        ax += v.x; ay += v.y; az += v.z; aw += v.w;
    }
    float dinv = g_Dinv[row];
    float4 b1 = hcb[lane];
    float4 b2 = linb[lane];
    const float4* linP = (const float4*)g_B;
    float4 l = linP[row * 32 + lane];
    float4 r;
    r.x = leakyf(ax * dinv + b1.x + b2.x + l.x);
    r.y = leakyf(ay * dinv + b1.y + b2.y + l.y);
    r.z = leakyf(az * dinv + b1.z + b2.z + l.z);
    r.w = leakyf(aw * dinv + b1.w + b2.w + l.w);
    ((float4*)dstbuf(outsel, 0))[row * 32 + lane] = r;
}

__global__ void gather_edge_kernel(int srcsel) {
    int row = (blockIdx.x * blockDim.x + threadIdx.x) >> 5;
    if (row >= NN) return;
    int lane = threadIdx.x & 31;
    int beg = g_off_nd[row], end = g_off_nd[row + 1];
    const float4* src = (const float4*)srcbuf(srcsel, 0);
    float ax = 0.f, ay = 0.f, az = 0.f, aw = 0.f;
    int i = beg;
    for (; i + 4 <= end; i += 4) {
        int n0 = g_list_nd[i], n1 = g_list_nd[i + 1], n2 = g_list_nd[i + 2], n3 = g_list_nd[i + 3];
        float4 v0 = src[n0 * 32 + lane];
        float4 v1 = src[n1 * 32 + lane];
        float4 v2 = src[n2 * 32 + lane];
        float4 v3 = src[n3 * 32 + lane];
        ax += (v0.x + v1.x) + (v2.x + v3.x);
        ay += (v0.y + v1.y) + (v2.y + v3.y);
        az += (v0.z + v1.z) + (v2.z + v3.z);
        aw += (v0.w + v1.w) + (v2.w + v3.w);
    }
    for (; i < end; ++i) {
        int n = g_list_nd[i];
        float4 v = src[n * 32 + lane];
        ax += v.x; ay += v.y; az += v.z; aw += v.w;
    }
    ((float4*)g_A)[row * 32 + lane] = make_float4(ax, ay, az, aw);
}

__global__ void combine_kernel(const float* __restrict__ a, const float* __restrict__ b,
                               const float* __restrict__ ba, const float* __restrict__ bb) {
    int i = blockIdx.x * blockDim.x + threadIdx.x;
    if (i < HID * HID) g_Wc[i] = a[i] + b[i];
    if (i < HID) g_bsum[i] = ba[i] + bb[i];
}

// ---------------- fp32 SGEMM (proven R4 version): C[M x Kout] = A[M x 128] @ W[128 x Kout] ----
// MODE 0: C = acc ; MODE 1: C = acc + bias_ext ; MODE 2: C = leaky(acc + g_B + g_bsum)
template <int MODE>
__global__ void gemm_kernel(const float* __restrict__ Aext, const float* __restrict__ Wext,
                            float* __restrict__ Cext, const float* __restrict__ bias_ext,
                            int asel, int csel, int wsel, int M, int Kout) {
    const float* A = srcbuf(asel, Aext);
    const float* W = (wsel == 1) ? g_Wc : Wext;
    float* C = dstbuf(csel, Cext);

    __shared__ float As[64][68];  // [m][kk], padded
    __shared__ float Ws[64][64];  // [kk][n]
    int tid = threadIdx.x;
    int tx = tid & 15, ty = tid >> 4;
    int brow = blockIdx.y * 64;
    int bcol = blockIdx.x * 64;

    float acc[4][4];
#pragma unroll
    for (int i = 0; i < 4; ++i)
#pragma unroll
        for (int j = 0; j < 4; ++j) acc[i][j] = 0.f;

    for (int ks = 0; ks < 128; ks += 64) {
#pragma unroll
        for (int p = 0; p < 4; ++p) {
            int r  = (tid >> 4) + p * 16;
            int k4 = (tid & 15);
            int gr = brow + r;
            float4 v = make_float4(0.f, 0.f, 0.f, 0.f);
            if (gr < M) v = *(const float4*)&A[gr * 128 + ks + k4 * 4];
            As[r][k4 * 4 + 0] = v.x;
            As[r][k4 * 4 + 1] = v.y;
            As[r][k4 * 4 + 2] = v.z;
            As[r][k4 * 4 + 3] = v.w;
        }
#pragma unroll
        for (int p = 0; p < 4; ++p) {
            int kk = (tid >> 4) + p * 16;
            int n4 = (tid & 15);
            float4 v = *(const float4*)&W[(ks + kk) * Kout + bcol + n4 * 4];
            *(float4*)&Ws[kk][n4 * 4] = v;
        }
        __syncthreads();
#pragma unroll 8
        for (int kk = 0; kk < 64; ++kk) {
            float a0 = As[ty * 4 + 0][kk];
            float a1 = As[ty * 4 + 1][kk];
            float a2 = As[ty * 4 + 2][kk];
            float a3 = As[ty * 4 + 3][kk];
            float4 w = *(const float4*)&Ws[kk][tx * 4];
            acc[0][0] += a0 * w.x; acc[0][1] += a0 * w.y; acc[0][2] += a0 * w.z; acc[0][3] += a0 * w.w;
            acc[1][0] += a1 * w.x; acc[1][1] += a1 * w.y; acc[1][2] += a1 * w.z; acc[1][3] += a1 * w.w;
            acc[2][0] += a2 * w.x; acc[2][1] += a2 * w.y; acc[2][2] += a2 * w.z; acc[2][3] += a2 * w.w;
            acc[3][0] += a3 * w.x; acc[3][1] += a3 * w.y; acc[3][2] += a3 * w.z; acc[3][3] += a3 * w.w;
        }
        __syncthreads();
    }

#pragma unroll
    for (int i = 0; i < 4; ++i) {
        int gr = brow + ty * 4 + i;
        if (gr >= M) continue;
#pragma unroll
        for (int j = 0; j < 4; ++j) {
            int gc = bcol + tx * 4 + j;
            float v = acc[i][j];
            if (MODE == 1) v += bias_ext[gc];
            if (MODE == 2) v = leakyf(v + g_B[gr * Kout + gc] + g_bsum[gc]);
            C[gr * Kout + gc] = v;
        }
    }
}

// ---------------- launch ----------------
extern "C" void kernel_launch(void* const* d_in, const int* in_sizes, int n_in,
                              void* d_out, int out_size) {
    const float* X     = (const float*)d_in[0];
    const int* eidx    = (const int*)d_in[1];   // int32 or int64 (auto-detected)
    const int* hidx    = (const int*)d_in[2];
    const float* hc1w  = (const float*)d_in[3];
    const float* hc1b  = (const float*)d_in[4];
    const float* lin1w = (const float*)d_in[5];
    const float* lin1b = (const float*)d_in[6];
    const float* hc2w  = (const float*)d_in[7];
    const float* hc2b  = (const float*)d_in[8];
    const float* lin2w = (const float*)d_in[9];
    const float* lin2b = (const float*)d_in[10];
    const float* c1wrel  = (const float*)d_in[11];
    const float* c1brel  = (const float*)d_in[12];
    const float* c1wroot = (const float*)d_in[13];
    const float* glin1w  = (const float*)d_in[14];
    const float* glin1b  = (const float*)d_in[15];
    const float* c2wrel  = (const float*)d_in[16];
    const float* c2brel  = (const float*)d_in[17];
    const float* c2wroot = (const float*)d_in[18];
    const float* glin2w  = (const float*)d_in[19];
    const float* glin2b  = (const float*)d_in[20];
    const float* fcw = (const float*)d_in[21];
    const float* fcb = (const float*)d_in[22];

    const size_t NX = (size_t)NN * HID;
    const size_t NYsz = (size_t)NN * OUTC;
    bool full_out = ((size_t)out_size >= NX + NYsz);
    float* outX = (float*)d_out;
    float* outY = full_out ? (outX + NX) : (float*)d_out;
    int final_csel = full_out ? -1 : 3;
    int fc_asel    = full_out ? -1 : 3;
    const float* fc_Aext = full_out ? outX : (const float*)0;

    const int TPB = 256;
    dim3 g2(2, (NN + 63) / 64);   // Kout=128
    dim3 g1(1, (NN + 63) / 64);   // Kout=64
    int gbE   = (NE + TPB - 1) / TPB;
    int gbHEw = (NHE * 32 + TPB - 1) / TPB;
    int gbNw  = (NN * 32 + TPB - 1) / TPB;

    // ---- dtype detect + CSR build ----
    detect_kernel<<<1, 256>>>(hidx);
    zero_deg_kernel<<<(NN + TPB - 1) / TPB, TPB>>>();
    count_kernel<<<gbE, TPB>>>(hidx, eidx);
    scan_kernel<<<3, 1024>>>();
    fill_kernel<<<gbE, TPB>>>(hidx, eidx);

    // ---- layer 1 (hypergraph) ----
    gemm_kernel<0><<<g2, TPB>>>(X, hc1w, 0, 0, -1, 0, 0, NN, 128);   // g_A = X @ hc1w
    gemm_kernel<0><<<g2, TPB>>>(X, lin1w, 0, 0, -1, 1, 0, NN, 128);  // g_B = X @ lin1w
    gather_he_kernel<<<gbHEw, TPB>>>();
    gather_node_fuse_kernel<<<gbNw, TPB>>>((const float4*)hc1b, (const float4*)lin1b, 2);  // -> g_X1

    // ---- layer 2 (hypergraph) ----
    gemm_kernel<0><<<g2, TPB>>>(0, hc2w, 0, 0, 2, 0, 0, NN, 128);    // g_A = g_X1 @ hc2w
    gemm_kernel<0><<<g2, TPB>>>(0, lin2w, 0, 0, 2, 1, 0, NN, 128);   // g_B = g_X1 @ lin2w
    gather_he_kernel<<<gbHEw, TPB>>>();
    gather_node_fuse_kernel<<<gbNw, TPB>>>((const float4*)hc2b, (const float4*)lin2b, 3);  // -> g_X2

    // ---- layer 3 (graph) ----
    combine_kernel<<<(HID * HID + TPB - 1) / TPB, TPB>>>(c1wroot, glin1w, c1brel, glin1b);
    gather_edge_kernel<<<gbNw, TPB>>>(3);                            // g_A = segsum(g_X2)
    gemm_kernel<0><<<g2, TPB>>>(0, c1wrel, 0, 0, 0, 1, 0, NN, 128);  // g_B = g_A @ c1wrel
    gemm_kernel<2><<<g2, TPB>>>(0, 0, 0, 0, 3, 2, 1, NN, 128);       // g_X1 = leaky(g_X2@Wc + g_B + bsum)

    // ---- layer 4 (graph) ----
    combine_kernel<<<(HID * HID + TPB - 1) / TPB, TPB>>>(c2wroot, glin2w, c2brel, glin2b);
    gather_edge_kernel<<<gbNw, TPB>>>(2);                            // g_A = segsum(g_X1)
    gemm_kernel<0><<<g2, TPB>>>(0, c2wrel, 0, 0, 0, 1, 0, NN, 128);  // g_B = g_A @ c2wrel
    gemm_kernel<2><<<g2, TPB>>>(0, 0, outX, 0, 2, final_csel, 1, NN, 128);  // X4

    // ---- fc head ----
    gemm_kernel<1><<<g1, TPB>>>(fc_Aext, fcw, outY, fcb, fc_asel, -1, 0, NN, 64);
}

// round 9
// speedup vs baseline: 1.8463x; 1.1660x over previous
#include <cuda_runtime.h>
#include <cstdint>

#define NN   50000
#define NHE  10000
#define NE   800000
#define NI   800000
#define HID  128
#define OUTC 64

// ---------------- device scratch ----------------
__device__ __align__(16) float g_A[NN * HID];
__device__ __align__(16) float g_B[NN * HID];
__device__ __align__(16) float g_X1[NN * HID];
__device__ __align__(16) float g_X2[NN * HID];
__device__ __align__(16) float g_M[NHE * HID];
__device__ __align__(16) float g_Wh[9 * 128 * 128];   // W^T hi parts, [w][n][k]
__device__ __align__(16) float g_Wl[9 * 128 * 128];   // W^T lo parts
__device__ __align__(16) float g_bsum1[HID];
__device__ __align__(16) float g_bsum2[HID];
__device__ __align__(16) float g_Binv[NHE];
__device__ __align__(16) float g_Dinv[NN];

__device__ int g_idx64;
__device__ __align__(16) int g_deg_he[NHE];
__device__ __align__(16) int g_off_he[NHE + 1];
__device__ __align__(16) int g_cur_he[NHE];
__device__ __align__(16) int g_deg_nh[NN];
__device__ __align__(16) int g_off_nh[NN + 1];
__device__ __align__(16) int g_cur_nh[NN];
__device__ __align__(16) int g_deg_nd[NN];
__device__ __align__(16) int g_off_nd[NN + 1];
__device__ __align__(16) int g_cur_nd[NN];
__device__ int g_list_he[NI];
__device__ int g_list_nh[NI];
__device__ int g_list_nd[NE];

__device__ __forceinline__ float leakyf(float x) { return x >= 0.f ? x : 0.01f * x; }
__device__ __forceinline__ int clampi(int v, int hi) { return v < 0 ? 0 : (v >= hi ? hi - 1 : v); }

__device__ __forceinline__ int idxat(const int* __restrict__ a, int pos) {
    return g_idx64 ? a[2 * (long long)pos] : a[pos];
}

__device__ __forceinline__ const float* srcbuf(int id, const float* ext) {
    switch (id) {
        case 0: return g_A;
        case 1: return g_B;
        case 2: return g_X1;
        case 3: return g_X2;
        default: return ext;
    }
}
__device__ __forceinline__ float* dstbuf(int id, float* ext) {
    switch (id) {
        case 0: return g_A;
        case 1: return g_B;
        case 2: return g_X1;
        case 3: return g_X2;
        default: return ext;
    }
}

__device__ __forceinline__ uint32_t f2tf(float x) {
    uint32_t r; asm("cvt.rna.tf32.f32 %0, %1;" : "=r"(r) : "f"(x)); return r;
}

__device__ __forceinline__ void mma8(float c[4], uint32_t a0, uint32_t a1, uint32_t a2, uint32_t a3,
                                     uint32_t b0, uint32_t b1) {
    asm volatile("mma.sync.aligned.m16n8k8.row.col.f32.tf32.tf32.f32 "
                 "{%0,%1,%2,%3},{%4,%5,%6,%7},{%8,%9},{%0,%1,%2,%3};"
                 : "+f"(c[0]), "+f"(c[1]), "+f"(c[2]), "+f"(c[3])
                 : "r"(a0), "r"(a1), "r"(a2), "r"(a3), "r"(b0), "r"(b1));
}

// ---------------- index dtype detect ----------------
__global__ void detect_kernel(const int* __restrict__ he) {
    __shared__ int any;
    if (threadIdx.x == 0) any = 0;
    __syncthreads();
    if (he[2 * threadIdx.x + 1] != 0) atomicOr(&any, 1);
    __syncthreads();
    if (threadIdx.x == 0) g_idx64 = (any == 0) ? 1 : 0;
}

// ---------------- weight prep: transpose + tf32 hi/lo decompose (sum of two srcs optional) ----
struct WList { const float* a[9]; const float* b[9]; int ncols[9]; };

__global__ void decompose_kernel(WList wl) {
    int w = blockIdx.y;
    int i = blockIdx.x * blockDim.x + threadIdx.x;   // 0..16383
    int k = i >> 7;
    int n = i & 127;
    int NC = wl.ncols[w];
    if (n >= NC) return;
    float v = wl.a[w][k * NC + n];
    if (wl.b[w]) v += wl.b[w][k * NC + n];
    uint32_t hb = f2tf(v);
    float h = __uint_as_float(hb);
    g_Wh[w * 16384 + n * 128 + k] = h;
    g_Wl[w * 16384 + n * 128 + k] = v - h;
}

__global__ void bias_combine_kernel(const float* __restrict__ a1, const float* __restrict__ b1,
                                    const float* __restrict__ a2, const float* __restrict__ b2) {
    int i = threadIdx.x;
    if (i < HID) { g_bsum1[i] = a1[i] + b1[i]; g_bsum2[i] = a2[i] + b2[i]; }
}

// ---------------- CSR build ----------------
__global__ void zero_deg_kernel() {
    int i = blockIdx.x * blockDim.x + threadIdx.x;
    if (i < NHE) g_deg_he[i] = 0;
    if (i < NN) { g_deg_nh[i] = 0; g_deg_nd[i] = 0; }
}

__global__ void count_kernel(const int* __restrict__ he, const int* __restrict__ ed) {
    int i = blockIdx.x * blockDim.x + threadIdx.x;
    if (i < NI) {
        atomicAdd(&g_deg_nh[clampi(idxat(he, i), NN)], 1);
        atomicAdd(&g_deg_he[clampi(idxat(he, NI + i), NHE)], 1);
    }
    if (i < NE) {
        atomicAdd(&g_deg_nd[clampi(idxat(ed, NE + i), NN)], 1);
    }
}

// fast two-level shuffle scan; 3 independent scans, blockIdx.x = which
__global__ void scan_kernel() {
    int which = blockIdx.x;
    const int* __restrict__ deg; int n; int* __restrict__ off; int* __restrict__ cur;
    float* __restrict__ inv;
    if (which == 0)      { deg = g_deg_he; n = NHE; off = g_off_he; cur = g_cur_he; inv = g_Binv; }
    else if (which == 1) { deg = g_deg_nh; n = NN;  off = g_off_nh; cur = g_cur_nh; inv = g_Dinv; }
    else                 { deg = g_deg_nd; n = NN;  off = g_off_nd; cur = g_cur_nd; inv = 0; }

    __shared__ int wsum[32];
    __shared__ int s_tot;
    __shared__ int s_run;
    int tid = threadIdx.x;
    int lane = tid & 31, wid = tid >> 5;
    if (tid == 0) s_run = 0;
    __syncthreads();

    int nt = (n + 4095) / 4096;
    for (int t = 0; t < nt; ++t) {
        int base = t * 4096 + tid * 4;
        int d0 = 0, d1 = 0, d2 = 0, d3 = 0;
        if (base + 3 < n) {
            int4 v = *(const int4*)&deg[base];
            d0 = v.x; d1 = v.y; d2 = v.z; d3 = v.w;
        } else {
            if (base + 0 < n) d0 = deg[base + 0];
            if (base + 1 < n) d1 = deg[base + 1];
            if (base + 2 < n) d2 = deg[base + 2];
            if (base + 3 < n) d3 = deg[base + 3];
        }
        int s = d0 + d1 + d2 + d3;
        int incl = s;
#pragma unroll
        for (int o = 1; o < 32; o <<= 1) {
            int v = __shfl_up_sync(0xFFFFFFFFu, incl, o);
            if (lane >= o) incl += v;
        }
        if (lane == 31) wsum[wid] = incl;
        __syncthreads();
        if (wid == 0) {
            int ws = wsum[lane];
            int wincl = ws;
#pragma unroll
            for (int o = 1; o < 32; o <<= 1) {
                int v = __shfl_up_sync(0xFFFFFFFFu, wincl, o);
                if (lane >= o) wincl += v;
            }
            wsum[lane] = wincl - ws;
            if (lane == 31) s_tot = wincl;
        }
        __syncthreads();
        int excl = s_run + wsum[wid] + (incl - s);
        int o0 = excl, o1 = o0 + d0, o2 = o1 + d1, o3 = o2 + d2;
        if (base + 3 < n) {
            *(int4*)&off[base] = make_int4(o0, o1, o2, o3);
            *(int4*)&cur[base] = make_int4(o0, o1, o2, o3);
            if (inv) {
                float4 f;
                f.x = d0 ? 1.0f / (float)d0 : 0.0f;
                f.y = d1 ? 1.0f / (float)d1 : 0.0f;
                f.z = d2 ? 1.0f / (float)d2 : 0.0f;
                f.w = d3 ? 1.0f / (float)d3 : 0.0f;
                *(float4*)&inv[base] = f;
            }
        } else {
            if (base + 0 < n) { off[base + 0] = o0; cur[base + 0] = o0; if (inv) inv[base + 0] = d0 ? 1.0f / (float)d0 : 0.0f; }
            if (base + 1 < n) { off[base + 1] = o1; cur[base + 1] = o1; if (inv) inv[base + 1] = d1 ? 1.0f / (float)d1 : 0.0f; }
            if (base + 2 < n) { off[base + 2] = o2; cur[base + 2] = o2; if (inv) inv[base + 2] = d2 ? 1.0f / (float)d2 : 0.0f; }
            if (base + 3 < n) { off[base + 3] = o3; cur[base + 3] = o3; if (inv) inv[base + 3] = d3 ? 1.0f / (float)d3 : 0.0f; }
        }
        __syncthreads();
        if (tid == 0) s_run += s_tot;
        __syncthreads();
    }
    if (tid == 0) off[n] = s_run;
}

__global__ void fill_kernel(const int* __restrict__ he, const int* __restrict__ ed) {
    int i = blockIdx.x * blockDim.x + threadIdx.x;
    if (i < NI) {
        int n = clampi(idxat(he, i), NN);
        int h = clampi(idxat(he, NI + i), NHE);
        g_list_he[atomicAdd(&g_cur_he[h], 1)] = n;
        g_list_nh[atomicAdd(&g_cur_nh[n], 1)] = h;
    }
    if (i < NE) {
        int s = clampi(idxat(ed, i), NN);
        int d = clampi(idxat(ed, NE + i), NN);
        g_list_nd[atomicAdd(&g_cur_nd[d], 1)] = s;
    }
}

// ---------------- gather segment-sums (1 warp per output row) ----------------
__global__ void gather_he_kernel() {
    int row = (blockIdx.x * blockDim.x + threadIdx.x) >> 5;
    if (row >= NHE) return;
    int lane = threadIdx.x & 31;
    int beg = g_off_he[row], end = g_off_he[row + 1];
    const float4* src = (const float4*)g_A;
    float ax = 0.f, ay = 0.f, az = 0.f, aw = 0.f;
    int i = beg;
    for (; i + 4 <= end; i += 4) {
        int n0 = g_list_he[i], n1 = g_list_he[i + 1], n2 = g_list_he[i + 2], n3 = g_list_he[i + 3];
        float4 v0 = src[n0 * 32 + lane];
        float4 v1 = src[n1 * 32 + lane];
        float4 v2 = src[n2 * 32 + lane];
        float4 v3 = src[n3 * 32 + lane];
        ax += (v0.x + v1.x) + (v2.x + v3.x);
        ay += (v0.y + v1.y) + (v2.y + v3.y);
        az += (v0.z + v1.z) + (v2.z + v3.z);
        aw += (v0.w + v1.w) + (v2.w + v3.w);
    }
    for (; i < end; ++i) {
        int n = g_list_he[i];
        float4 v = src[n * 32 + lane];
        ax += v.x; ay += v.y; az += v.z; aw += v.w;
    }
    float b = g_Binv[row];
    ((float4*)g_M)[row * 32 + lane] = make_float4(ax * b, ay * b, az * b, aw * b);
}

__global__ void gather_node_fuse_kernel(const float4* __restrict__ hcb,
                                        const float4* __restrict__ linb,
                                        int outsel) {
    int row = (blockIdx.x * blockDim.x + threadIdx.x) >> 5;
    if (row >= NN) return;
    int lane = threadIdx.x & 31;
    int beg = g_off_nh[row], end = g_off_nh[row + 1];
    const float4* m = (const float4*)g_M;
    float ax = 0.f, ay = 0.f, az = 0.f, aw = 0.f;
    int i = beg;
    for (; i + 4 <= end; i += 4) {
        int h0 = g_list_nh[i], h1 = g_list_nh[i + 1], h2 = g_list_nh[i + 2], h3 = g_list_nh[i + 3];
        float4 v0 = m[h0 * 32 + lane];
        float4 v1 = m[h1 * 32 + lane];
        float4 v2 = m[h2 * 32 + lane];
        float4 v3 = m[h3 * 32 + lane];
        ax += (v0.x + v1.x) + (v2.x + v3.x);
        ay += (v0.y + v1.y) + (v2.y + v3.y);
        az += (v0.z + v1.z) + (v2.z + v3.z);
        aw += (v0.w + v1.w) + (v2.w + v3.w);
    }
    for (; i < end; ++i) {
        int h = g_list_nh[i];
        float4 v = m[h * 32 + lane];
        ax += v.x; ay += v.y; az += v.z; aw += v.w;
    }
    float dinv = g_Dinv[row];
    float4 b1 = hcb[lane];
    float4 b2 = linb[lane];
    const float4* linP = (const float4*)g_B;
    float4 l = linP[row * 32 + lane];
    float4 r;
    r.x = leakyf(ax * dinv + b1.x + b2.x + l.x);
    r.y = leakyf(ay * dinv + b1.y + b2.y + l.y);
    r.z = leakyf(az * dinv + b1.z + b2.z + l.z);
    r.w = leakyf(aw * dinv + b1.w + b2.w + l.w);
    ((float4*)dstbuf(outsel, 0))[row * 32 + lane] = r;
}

__global__ void gather_edge_kernel(int srcsel) {
    int row = (blockIdx.x * blockDim.x + threadIdx.x) >> 5;
    if (row >= NN) return;
    int lane = threadIdx.x & 31;
    int beg = g_off_nd[row], end = g_off_nd[row + 1];
    const float4* src = (const float4*)srcbuf(srcsel, 0);
    float ax = 0.f, ay = 0.f, az = 0.f, aw = 0.f;
    int i = beg;
    for (; i + 4 <= end; i += 4) {
        int n0 = g_list_nd[i], n1 = g_list_nd[i + 1], n2 = g_list_nd[i + 2], n3 = g_list_nd[i + 3];
        float4 v0 = src[n0 * 32 + lane];
        float4 v1 = src[n1 * 32 + lane];
        float4 v2 = src[n2 * 32 + lane];
        float4 v3 = src[n3 * 32 + lane];
        ax += (v0.x + v1.x) + (v2.x + v3.x);
        ay += (v0.y + v1.y) + (v2.y + v3.y);
        az += (v0.z + v1.z) + (v2.z + v3.z);
        aw += (v0.w + v1.w) + (v2.w + v3.w);
    }
    for (; i < end; ++i) {
        int n = g_list_nd[i];
        float4 v = src[n * 32 + lane];
        ax += v.x; ay += v.y; az += v.z; aw += v.w;
    }
    ((float4*)g_A)[row * 32 + lane] = make_float4(ax, ay, az, aw);
}

// ---------------- 3xTF32 tensor-core GEMM ----------------
// C[M x KOUT] = A[M x 128] @ W[128 x KOUT] via precomputed Wt hi/lo (widx).
// MODE 0: C = acc ; MODE 1: C = acc + bias_ext ; MODE 2: C = leaky(acc + g_B + bsum)
// Block: 256 thr (8 warps), tile 128 x KOUT, K-chunks of 64.
template <int MODE, int NT>
__global__ __launch_bounds__(256, 2)
void gemm_tf32(const float* __restrict__ Aext, float* __restrict__ Cext,
               const float* __restrict__ bias_ext, int asel, int csel, int widx,
               int bs, int M) {
    constexpr int KOUT = NT * 8;
    const float* A = srcbuf(asel, Aext);
    float* C = dstbuf(csel, Cext);
    const float* Wh = g_Wh + widx * 16384;
    const float* Wl = g_Wl + widx * 16384;

    extern __shared__ float sm[];
    float* As = sm;                   // [128][68]
    float* Bh = sm + 128 * 68;        // [128][68]
    float* Bl = Bh + 128 * 68;        // [128][68]

    int tid = threadIdx.x;
    int lane = tid & 31, warp = tid >> 5;
    int g = lane >> 2, t = lane & 3;
    int brow = blockIdx.x * 128;
    int wr = warp * 16;

    float c[NT][4];
#pragma unroll
    for (int nt = 0; nt < NT; ++nt)
#pragma unroll
        for (int j = 0; j < 4; ++j) c[nt][j] = 0.f;

#pragma unroll
    for (int chunk = 0; chunk < 2; ++chunk) {
        int k0 = chunk * 64;
        if (chunk) __syncthreads();
        // stage A chunk [128 rows][64 k]
#pragma unroll
        for (int p = 0; p < 8; ++p) {
            int idx = p * 256 + tid;
            int r = idx >> 4, c4 = (idx & 15) * 4;
            int gr = brow + r;
            float4 v = make_float4(0.f, 0.f, 0.f, 0.f);
            if (gr < M) v = *(const float4*)&A[(size_t)gr * 128 + k0 + c4];
            *(float4*)&As[r * 68 + c4] = v;
        }
        // stage B chunk [KOUT n][64 k] hi+lo
#pragma unroll
        for (int p = 0; p < 8; ++p) {
            int idx = p * 256 + tid;
            int n = idx >> 4, c4 = (idx & 15) * 4;
            if (n < KOUT) {
                *(float4*)&Bh[n * 68 + c4] = *(const float4*)&Wh[n * 128 + k0 + c4];
                *(float4*)&Bl[n * 68 + c4] = *(const float4*)&Wl[n * 128 + k0 + c4];
            }
        }
        __syncthreads();

#pragma unroll
        for (int kt = 0; kt < 8; ++kt) {
            int kk = kt * 8;
            float a0 = As[(wr + g) * 68 + kk + t];
            float a1 = As[(wr + g + 8) * 68 + kk + t];
            float a2 = As[(wr + g) * 68 + kk + t + 4];
            float a3 = As[(wr + g + 8) * 68 + kk + t + 4];
            uint32_t ah0 = f2tf(a0), ah1 = f2tf(a1), ah2 = f2tf(a2), ah3 = f2tf(a3);
            uint32_t al0 = __float_as_uint(a0 - __uint_as_float(ah0));
            uint32_t al1 = __float_as_uint(a1 - __uint_as_float(ah1));
            uint32_t al2 = __float_as_uint(a2 - __uint_as_float(ah2));
            uint32_t al3 = __float_as_uint(a3 - __uint_as_float(ah3));
#pragma unroll
            for (int nt = 0; nt < NT; ++nt) {
                int nb = (nt * 8 + g) * 68 + kk;
                uint32_t b0h = __float_as_uint(Bh[nb + t]);
                uint32_t b1h = __float_as_uint(Bh[nb + t + 4]);
                uint32_t b0l = __float_as_uint(Bl[nb + t]);
                uint32_t b1l = __float_as_uint(Bl[nb + t + 4]);
                mma8(c[nt], ah0, ah1, ah2, ah3, b0h, b1h);
                mma8(c[nt], al0, al1, al2, al3, b0h, b1h);
                mma8(c[nt], ah0, ah1, ah2, ah3, b0l, b1l);
            }
        }
    }

    // epilogue
    const float* bsum = bs ? g_bsum2 : g_bsum1;
    int r0 = brow + wr + g;
    int r1 = r0 + 8;
#pragma unroll
    for (int nt = 0; nt < NT; ++nt) {
        int col = nt * 8 + 2 * t;
        if (r0 < M) {
            float v0 = c[nt][0], v1 = c[nt][1];
            if (MODE == 1) { v0 += bias_ext[col]; v1 += bias_ext[col + 1]; }
            if (MODE == 2) {
                v0 = leakyf(v0 + g_B[(size_t)r0 * 128 + col] + bsum[col]);
                v1 = leakyf(v1 + g_B[(size_t)r0 * 128 + col + 1] + bsum[col + 1]);
            }
            *(float2*)&C[(size_t)r0 * KOUT + col] = make_float2(v0, v1);
        }
        if (r1 < M) {
            float v2 = c[nt][2], v3 = c[nt][3];
            if (MODE == 1) { v2 += bias_ext[col]; v3 += bias_ext[col + 1]; }
            if (MODE == 2) {
                v2 = leakyf(v2 + g_B[(size_t)r1 * 128 + col] + bsum[col]);
                v3 = leakyf(v3 + g_B[(size_t)r1 * 128 + col + 1] + bsum[col + 1]);
            }
            *(float2*)&C[(size_t)r1 * KOUT + col] = make_float2(v2, v3);
        }
    }
}

// ---------------- launch ----------------
extern "C" void kernel_launch(void* const* d_in, const int* in_sizes, int n_in,
                              void* d_out, int out_size) {
    const float* X     = (const float*)d_in[0];
    const int* eidx    = (const int*)d_in[1];
    const int* hidx    = (const int*)d_in[2];
    const float* hc1w  = (const float*)d_in[3];
    const float* hc1b  = (const float*)d_in[4];
    const float* lin1w = (const float*)d_in[5];
    const float* lin1b = (const float*)d_in[6];
    const float* hc2w  = (const float*)d_in[7];
    const float* hc2b  = (const float*)d_in[8];
    const float* lin2w = (const float*)d_in[9];
    const float* lin2b = (const float*)d_in[10];
    const float* c1wrel  = (const float*)d_in[11];
    const float* c1brel  = (const float*)d_in[12];
    const float* c1wroot = (const float*)d_in[13];
    const float* glin1w  = (const float*)d_in[14];
    const float* glin1b  = (const float*)d_in[15];
    const float* c2wrel  = (const float*)d_in[16];
    const float* c2brel  = (const float*)d_in[17];
    const float* c2wroot = (const float*)d_in[18];
    const float* glin2w  = (const float*)d_in[19];
    const float* glin2b  = (const float*)d_in[20];
    const float* fcw = (const float*)d_in[21];
    const float* fcb = (const float*)d_in[22];

    const size_t NX = (size_t)NN * HID;
    const size_t NYsz = (size_t)NN * OUTC;
    bool full_out = ((size_t)out_size >= NX + NYsz);
    float* outX = (float*)d_out;
    float* outY = full_out ? (outX + NX) : (float*)d_out;
    int final_csel = full_out ? -1 : 3;
    int fc_asel    = full_out ? -1 : 3;
    const float* fc_Aext = full_out ? outX : (const float*)0;

    const int TPB = 256;
    const int SMEMSZ = 3 * 128 * 68 * 4;    // 104448 B dynamic smem
    int gG = (NN + 127) / 128;
    int gbE   = (NE + TPB - 1) / TPB;
    int gbHEw = (NHE * 32 + TPB - 1) / TPB;
    int gbNw  = (NN * 32 + TPB - 1) / TPB;

    cudaFuncSetAttribute((const void*)gemm_tf32<0, 16>, cudaFuncAttributeMaxDynamicSharedMemorySize, SMEMSZ);
    cudaFuncSetAttribute((const void*)gemm_tf32<2, 16>, cudaFuncAttributeMaxDynamicSharedMemorySize, SMEMSZ);
    cudaFuncSetAttribute((const void*)gemm_tf32<1, 8>,  cudaFuncAttributeMaxDynamicSharedMemorySize, SMEMSZ);

    // ---- weight prep (independent of CSR) ----
    WList wl;
    wl.a[0] = hc1w;    wl.b[0] = 0;      wl.ncols[0] = 128;
    wl.a[1] = lin1w;   wl.b[1] = 0;      wl.ncols[1] = 128;
    wl.a[2] = hc2w;    wl.b[2] = 0;      wl.ncols[2] = 128;
    wl.a[3] = lin2w;   wl.b[3] = 0;      wl.ncols[3] = 128;
    wl.a[4] = c1wrel;  wl.b[4] = 0;      wl.ncols[4] = 128;
    wl.a[5] = c1wroot; wl.b[5] = glin1w; wl.ncols[5] = 128;
    wl.a[6] = c2wrel;  wl.b[6] = 0;      wl.ncols[6] = 128;
    wl.a[7] = c2wroot; wl.b[7] = glin2w; wl.ncols[7] = 128;
    wl.a[8] = fcw;     wl.b[8] = 0;      wl.ncols[8] = 64;
    decompose_kernel<<<dim3(64, 9), TPB>>>(wl);
    bias_combine_kernel<<<1, 128>>>(c1brel, glin1b, c2brel, glin2b);

    // ---- dtype detect + CSR build ----
    detect_kernel<<<1, 256>>>(hidx);
    zero_deg_kernel<<<(NN + TPB - 1) / TPB, TPB>>>();
    count_kernel<<<gbE, TPB>>>(hidx, eidx);
    scan_kernel<<<3, 1024>>>();
    fill_kernel<<<gbE, TPB>>>(hidx, eidx);

    // ---- layer 1 (hypergraph) ----
    gemm_tf32<0, 16><<<gG, TPB, SMEMSZ>>>(X, 0, 0, -1, 0, 0, 0, NN);   // g_A = X @ hc1w
    gemm_tf32<0, 16><<<gG, TPB, SMEMSZ>>>(X, 0, 0, -1, 1, 1, 0, NN);   // g_B = X @ lin1w
    gather_he_kernel<<<gbHEw, TPB>>>();
    gather_node_fuse_kernel<<<gbNw, TPB>>>((const float4*)hc1b, (const float4*)lin1b, 2);

    // ---- layer 2 (hypergraph) ----
    gemm_tf32<0, 16><<<gG, TPB, SMEMSZ>>>(0, 0, 0, 2, 0, 2, 0, NN);    // g_A = g_X1 @ hc2w
    gemm_tf32<0, 16><<<gG, TPB, SMEMSZ>>>(0, 0, 0, 2, 1, 3, 0, NN);    // g_B = g_X1 @ lin2w
    gather_he_kernel<<<gbHEw, TPB>>>();
    gather_node_fuse_kernel<<<gbNw, TPB>>>((const float4*)hc2b, (const float4*)lin2b, 3);

    // ---- layer 3 (graph) ----
    gather_edge_kernel<<<gbNw, TPB>>>(3);                              // g_A = segsum(g_X2)
    gemm_tf32<0, 16><<<gG, TPB, SMEMSZ>>>(0, 0, 0, 0, 1, 4, 0, NN);    // g_B = g_A @ c1wrel
    gemm_tf32<2, 16><<<gG, TPB, SMEMSZ>>>(0, 0, 0, 3, 2, 5, 0, NN);    // g_X1 = leaky(g_X2@Wc1 + g_B + bsum1)

    // ---- layer 4 (graph) ----
    gather_edge_kernel<<<gbNw, TPB>>>(2);                              // g_A = segsum(g_X1)
    gemm_tf32<0, 16><<<gG, TPB, SMEMSZ>>>(0, 0, 0, 0, 1, 6, 0, NN);    // g_B = g_A @ c2wrel
    gemm_tf32<2, 16><<<gG, TPB, SMEMSZ>>>(0, outX, 0, 2, final_csel, 7, 1, NN);  // X4

    // ---- fc head ----
    gemm_tf32<1, 8><<<gG, TPB, SMEMSZ>>>(fc_Aext, outY, fcb, fc_asel, -1, 8, 0, NN);
}

// round 10
// speedup vs baseline: 1.8726x; 1.0143x over previous
#include <cuda_runtime.h>
#include <cstdint>

#define NN   50000
#define NHE  10000
#define NE   800000
#define NI   800000
#define HID  128
#define OUTC 64

// ---------------- device scratch ----------------
__device__ __align__(16) float g_A[NN * HID];
__device__ __align__(16) float g_B[NN * HID];
__device__ __align__(16) float g_X1[NN * HID];
__device__ __align__(16) float g_X2[NN * HID];
__device__ __align__(16) float g_M[NHE * HID];
// packed tf32 weights: per w, [chunk(2)][kt(8)][n(128)][t(4)] float4 = (b0h,b1h,b0l,b1l)
__device__ __align__(16) float4 g_Wp[9 * 8192];
__device__ __align__(16) float g_bsum1[HID];
__device__ __align__(16) float g_bsum2[HID];
__device__ __align__(16) float g_Binv[NHE];
__device__ __align__(16) float g_Dinv[NN];

__device__ int g_idx64;
__device__ __align__(16) int g_deg_he[NHE];
__device__ __align__(16) int g_off_he[NHE + 1];
__device__ __align__(16) int g_cur_he[NHE];
__device__ __align__(16) int g_deg_nh[NN];
__device__ __align__(16) int g_off_nh[NN + 1];
__device__ __align__(16) int g_cur_nh[NN];
__device__ __align__(16) int g_deg_nd[NN];
__device__ __align__(16) int g_off_nd[NN + 1];
__device__ __align__(16) int g_cur_nd[NN];
__device__ int g_list_he[NI];
__device__ int g_list_nh[NI];
__device__ int g_list_nd[NE];

__device__ __forceinline__ float leakyf(float x) { return x >= 0.f ? x : 0.01f * x; }
__device__ __forceinline__ int clampi(int v, int hi) { return v < 0 ? 0 : (v >= hi ? hi - 1 : v); }

__device__ __forceinline__ int idxat(const int* __restrict__ a, int pos) {
    return g_idx64 ? a[2 * (long long)pos] : a[pos];
}

__device__ __forceinline__ const float* srcbuf(int id, const float* ext) {
    switch (id) {
        case 0: return g_A;
        case 1: return g_B;
        case 2: return g_X1;
        case 3: return g_X2;
        default: return ext;
    }
}
__device__ __forceinline__ float* dstbuf(int id, float* ext) {
    switch (id) {
        case 0: return g_A;
        case 1: return g_B;
        case 2: return g_X1;
        case 3: return g_X2;
        default: return ext;
    }
}

__device__ __forceinline__ uint32_t f2tf(float x) {
    uint32_t r; asm("cvt.rna.tf32.f32 %0, %1;" : "=r"(r) : "f"(x)); return r;
}

__device__ __forceinline__ void mma8(float c[4], uint32_t a0, uint32_t a1, uint32_t a2, uint32_t a3,
                                     uint32_t b0, uint32_t b1) {
    asm volatile("mma.sync.aligned.m16n8k8.row.col.f32.tf32.tf32.f32 "
                 "{%0,%1,%2,%3},{%4,%5,%6,%7},{%8,%9},{%0,%1,%2,%3};"
                 : "+f"(c[0]), "+f"(c[1]), "+f"(c[2]), "+f"(c[3])
                 : "r"(a0), "r"(a1), "r"(a2), "r"(a3), "r"(b0), "r"(b1));
}

// ---------------- index dtype detect ----------------
__global__ void detect_kernel(const int* __restrict__ he) {
    __shared__ int any;
    if (threadIdx.x == 0) any = 0;
    __syncthreads();
    if (he[2 * threadIdx.x + 1] != 0) atomicOr(&any, 1);
    __syncthreads();
    if (threadIdx.x == 0) g_idx64 = (any == 0) ? 1 : 0;
}

// ---------------- weight prep: transpose + tf32 hi/lo decompose into packed fragments ----
struct WList { const float* a[9]; const float* b[9]; int ncols[9]; };

__global__ void decompose_kernel(WList wl) {
    int w = blockIdx.y;
    int i = blockIdx.x * blockDim.x + threadIdx.x;   // 0..8191
    int t = i & 3, n = (i >> 2) & 127, kt = (i >> 9) & 7, c = i >> 12;
    int NC = wl.ncols[w];
    int k1 = c * 64 + kt * 8 + t, k2 = k1 + 4;
    float v1 = 0.f, v2 = 0.f;
    if (n < NC) {
        v1 = wl.a[w][k1 * NC + n];
        v2 = wl.a[w][k2 * NC + n];
        if (wl.b[w]) { v1 += wl.b[w][k1 * NC + n]; v2 += wl.b[w][k2 * NC + n]; }
    }
    float h1 = __uint_as_float(f2tf(v1));
    float h2 = __uint_as_float(f2tf(v2));
    g_Wp[w * 8192 + i] = make_float4(h1, h2, v1 - h1, v2 - h2);
}

__global__ void bias_combine_kernel(const float* __restrict__ a1, const float* __restrict__ b1,
                                    const float* __restrict__ a2, const float* __restrict__ b2) {
    int i = threadIdx.x;
    if (i < HID) { g_bsum1[i] = a1[i] + b1[i]; g_bsum2[i] = a2[i] + b2[i]; }
}

// ---------------- CSR build ----------------
__global__ void zero_deg_kernel() {
    int i = blockIdx.x * blockDim.x + threadIdx.x;
    if (i < NHE) g_deg_he[i] = 0;
    if (i < NN) { g_deg_nh[i] = 0; g_deg_nd[i] = 0; }
}

__global__ void count_kernel(const int* __restrict__ he, const int* __restrict__ ed) {
    int i = blockIdx.x * blockDim.x + threadIdx.x;
    if (i < NI) {
        atomicAdd(&g_deg_nh[clampi(idxat(he, i), NN)], 1);
        atomicAdd(&g_deg_he[clampi(idxat(he, NI + i), NHE)], 1);
    }
    if (i < NE) {
        atomicAdd(&g_deg_nd[clampi(idxat(ed, NE + i), NN)], 1);
    }
}

// fast two-level shuffle scan; 3 independent scans, blockIdx.x = which
__global__ void scan_kernel() {
    int which = blockIdx.x;
    const int* __restrict__ deg; int n; int* __restrict__ off; int* __restrict__ cur;
    float* __restrict__ inv;
    if (which == 0)      { deg = g_deg_he; n = NHE; off = g_off_he; cur = g_cur_he; inv = g_Binv; }
    else if (which == 1) { deg = g_deg_nh; n = NN;  off = g_off_nh; cur = g_cur_nh; inv = g_Dinv; }
    else                 { deg = g_deg_nd; n = NN;  off = g_off_nd; cur = g_cur_nd; inv = 0; }

    __shared__ int wsum[32];
    __shared__ int s_tot;
    __shared__ int s_run;
    int tid = threadIdx.x;
    int lane = tid & 31, wid = tid >> 5;
    if (tid == 0) s_run = 0;
    __syncthreads();

    int nt = (n + 4095) / 4096;
    for (int t = 0; t < nt; ++t) {
        int base = t * 4096 + tid * 4;
        int d0 = 0, d1 = 0, d2 = 0, d3 = 0;
        if (base + 3 < n) {
            int4 v = *(const int4*)&deg[base];
            d0 = v.x; d1 = v.y; d2 = v.z; d3 = v.w;
        } else {
            if (base + 0 < n) d0 = deg[base + 0];
            if (base + 1 < n) d1 = deg[base + 1];
            if (base + 2 < n) d2 = deg[base + 2];
            if (base + 3 < n) d3 = deg[base + 3];
        }
        int s = d0 + d1 + d2 + d3;
        int incl = s;
#pragma unroll
        for (int o = 1; o < 32; o <<= 1) {
            int v = __shfl_up_sync(0xFFFFFFFFu, incl, o);
            if (lane >= o) incl += v;
        }
        if (lane == 31) wsum[wid] = incl;
        __syncthreads();
        if (wid == 0) {
            int ws = wsum[lane];
            int wincl = ws;
#pragma unroll
            for (int o = 1; o < 32; o <<= 1) {
                int v = __shfl_up_sync(0xFFFFFFFFu, wincl, o);
                if (lane >= o) wincl += v;
            }
            wsum[lane] = wincl - ws;
            if (lane == 31) s_tot = wincl;
        }
        __syncthreads();
        int excl = s_run + wsum[wid] + (incl - s);
        int o0 = excl, o1 = o0 + d0, o2 = o1 + d1, o3 = o2 + d2;
        if (base + 3 < n) {
            *(int4*)&off[base] = make_int4(o0, o1, o2, o3);
            *(int4*)&cur[base] = make_int4(o0, o1, o2, o3);
            if (inv) {
                float4 f;
                f.x = d0 ? 1.0f / (float)d0 : 0.0f;
                f.y = d1 ? 1.0f / (float)d1 : 0.0f;
                f.z = d2 ? 1.0f / (float)d2 : 0.0f;
                f.w = d3 ? 1.0f / (float)d3 : 0.0f;
                *(float4*)&inv[base] = f;
            }
        } else {
            if (base + 0 < n) { off[base + 0] = o0; cur[base + 0] = o0; if (inv) inv[base + 0] = d0 ? 1.0f / (float)d0 : 0.0f; }
            if (base + 1 < n) { off[base + 1] = o1; cur[base + 1] = o1; if (inv) inv[base + 1] = d1 ? 1.0f / (float)d1 : 0.0f; }
            if (base + 2 < n) { off[base + 2] = o2; cur[base + 2] = o2; if (inv) inv[base + 2] = d2 ? 1.0f / (float)d2 : 0.0f; }
            if (base + 3 < n) { off[base + 3] = o3; cur[base + 3] = o3; if (inv) inv[base + 3] = d3 ? 1.0f / (float)d3 : 0.0f; }
        }
        __syncthreads();
        if (tid == 0) s_run += s_tot;
        __syncthreads();
    }
    if (tid == 0) off[n] = s_run;
}

__global__ void fill_kernel(const int* __restrict__ he, const int* __restrict__ ed) {
    int i = blockIdx.x * blockDim.x + threadIdx.x;
    if (i < NI) {
        int n = clampi(idxat(he, i), NN);
        int h = clampi(idxat(he, NI + i), NHE);
        g_list_he[atomicAdd(&g_cur_he[h], 1)] = n;
        g_list_nh[atomicAdd(&g_cur_nh[n], 1)] = h;
    }
    if (i < NE) {
        int s = clampi(idxat(ed, i), NN);
        int d = clampi(idxat(ed, NE + i), NN);
        g_list_nd[atomicAdd(&g_cur_nd[d], 1)] = s;
    }
}

// ---------------- gather segment-sums (1 warp per output row, 8-deep MLP) ----------------
#define GATHER_BODY(listarr, srcptr) \
    float ax = 0.f, ay = 0.f, az = 0.f, aw = 0.f; \
    int i = beg; \
    for (; i + 8 <= end; i += 8) { \
        int n0 = listarr[i], n1 = listarr[i + 1], n2 = listarr[i + 2], n3 = listarr[i + 3]; \
        int n4 = listarr[i + 4], n5 = listarr[i + 5], n6 = listarr[i + 6], n7 = listarr[i + 7]; \
        float4 v0 = srcptr[n0 * 32 + lane]; \
        float4 v1 = srcptr[n1 * 32 + lane]; \
        float4 v2 = srcptr[n2 * 32 + lane]; \
        float4 v3 = srcptr[n3 * 32 + lane]; \
        float4 v4 = srcptr[n4 * 32 + lane]; \
        float4 v5 = srcptr[n5 * 32 + lane]; \
        float4 v6 = srcptr[n6 * 32 + lane]; \
        float4 v7 = srcptr[n7 * 32 + lane]; \
        ax += ((v0.x + v1.x) + (v2.x + v3.x)) + ((v4.x + v5.x) + (v6.x + v7.x)); \
        ay += ((v0.y + v1.y) + (v2.y + v3.y)) + ((v4.y + v5.y) + (v6.y + v7.y)); \
        az += ((v0.z + v1.z) + (v2.z + v3.z)) + ((v4.z + v5.z) + (v6.z + v7.z)); \
        aw += ((v0.w + v1.w) + (v2.w + v3.w)) + ((v4.w + v5.w) + (v6.w + v7.w)); \
    } \
    for (; i < end; ++i) { \
        int nn_ = listarr[i]; \
        float4 v = srcptr[nn_ * 32 + lane]; \
        ax += v.x; ay += v.y; az += v.z; aw += v.w; \
    }

__global__ void gather_he_kernel() {
    int row = (blockIdx.x * blockDim.x + threadIdx.x) >> 5;
    if (row >= NHE) return;
    int lane = threadIdx.x & 31;
    int beg = g_off_he[row], end = g_off_he[row + 1];
    const float4* src = (const float4*)g_A;
    GATHER_BODY(g_list_he, src)
    float b = g_Binv[row];
    ((float4*)g_M)[row * 32 + lane] = make_float4(ax * b, ay * b, az * b, aw * b);
}

__global__ void gather_node_fuse_kernel(const float4* __restrict__ hcb,
                                        const float4* __restrict__ linb,
                                        int outsel) {
    int row = (blockIdx.x * blockDim.x + threadIdx.x) >> 5;
    if (row >= NN) return;
    int lane = threadIdx.x & 31;
    int beg = g_off_nh[row], end = g_off_nh[row + 1];
    const float4* m = (const float4*)g_M;
    GATHER_BODY(g_list_nh, m)
    float dinv = g_Dinv[row];
    float4 b1 = hcb[lane];
    float4 b2 = linb[lane];
    const float4* linP = (const float4*)g_B;
    float4 l = linP[row * 32 + lane];
    float4 r;
    r.x = leakyf(ax * dinv + b1.x + b2.x + l.x);
    r.y = leakyf(ay * dinv + b1.y + b2.y + l.y);
    r.z = leakyf(az * dinv + b1.z + b2.z + l.z);
    r.w = leakyf(aw * dinv + b1.w + b2.w + l.w);
    ((float4*)dstbuf(outsel, 0))[row * 32 + lane] = r;
}

__global__ void gather_edge_kernel(int srcsel) {
    int row = (blockIdx.x * blockDim.x + threadIdx.x) >> 5;
    if (row >= NN) return;
    int lane = threadIdx.x & 31;
    int beg = g_off_nd[row], end = g_off_nd[row + 1];
    const float4* src = (const float4*)srcbuf(srcsel, 0);
    GATHER_BODY(g_list_nd, src)
    ((float4*)g_A)[row * 32 + lane] = make_float4(ax, ay, az, aw);
}

// ---------------- 3xTF32 tensor-core GEMM with packed-B fragments ----------------
// C[M x KOUT] = A[M x 128] @ W[128 x KOUT]; W prepacked in g_Wp (widx).
// MODE 0: C = acc ; MODE 1: C = acc + bias_ext ; MODE 2: C = leaky(acc + g_B + bsum)
template <int MODE, int NT>
__global__ __launch_bounds__(256, 2)
void gemm_tf32(const float* __restrict__ Aext, float* __restrict__ Cext,
               const float* __restrict__ bias_ext, int asel, int csel, int widx,
               int bs, int M) {
    constexpr int KOUT = NT * 8;
    const float* A = srcbuf(asel, Aext);
    float* C = dstbuf(csel, Cext);

    extern __shared__ float sm[];
    float* As = sm;                           // [128][68]
    float4* Bs4 = (float4*)(sm + 128 * 68);   // [8 kt][128 n][4 t]

    int tid = threadIdx.x;
    int lane = tid & 31, warp = tid >> 5;
    int g = lane >> 2, t = lane & 3;
    int brow = blockIdx.x * 128;
    int wr = warp * 16;

    float c[NT][4];
#pragma unroll
    for (int nt = 0; nt < NT; ++nt)
#pragma unroll
        for (int j = 0; j < 4; ++j) c[nt][j] = 0.f;

#pragma unroll
    for (int chunk = 0; chunk < 2; ++chunk) {
        int k0 = chunk * 64;
        if (chunk) __syncthreads();
        // stage A chunk [128 rows][64 k]
#pragma unroll
        for (int p = 0; p < 8; ++p) {
            int idx = p * 256 + tid;
            int r = idx >> 4, c4 = (idx & 15) * 4;
            int gr = brow + r;
            float4 v = make_float4(0.f, 0.f, 0.f, 0.f);
            if (gr < M) v = *(const float4*)&A[(size_t)gr * 128 + k0 + c4];
            *(float4*)&As[r * 68 + c4] = v;
        }
        // stage packed B chunk: 4096 float4 straight copy
        const float4* Wp = g_Wp + widx * 8192 + chunk * 4096;
#pragma unroll
        for (int p = 0; p < 16; ++p) {
            int idx = p * 256 + tid;
            Bs4[idx] = Wp[idx];
        }
        __syncthreads();

#pragma unroll
        for (int kt = 0; kt < 8; ++kt) {
            int kk = kt * 8;
            float a0 = As[(wr + g) * 68 + kk + t];
            float a1 = As[(wr + g + 8) * 68 + kk + t];
            float a2 = As[(wr + g) * 68 + kk + t + 4];
            float a3 = As[(wr + g + 8) * 68 + kk + t + 4];
            uint32_t ah0 = f2tf(a0), ah1 = f2tf(a1), ah2 = f2tf(a2), ah3 = f2tf(a3);
            uint32_t al0 = __float_as_uint(a0 - __uint_as_float(ah0));
            uint32_t al1 = __float_as_uint(a1 - __uint_as_float(ah1));
            uint32_t al2 = __float_as_uint(a2 - __uint_as_float(ah2));
            uint32_t al3 = __float_as_uint(a3 - __uint_as_float(ah3));
#pragma unroll
            for (int nt = 0; nt < NT; ++nt) {
                float4 b = Bs4[kt * 512 + (nt * 8 + g) * 4 + t];
                uint32_t b0h = __float_as_uint(b.x);
                uint32_t b1h = __float_as_uint(b.y);
                uint32_t b0l = __float_as_uint(b.z);
                uint32_t b1l = __float_as_uint(b.w);
                mma8(c[nt], ah0, ah1, ah2, ah3, b0h, b1h);
                mma8(c[nt], al0, al1, al2, al3, b0h, b1h);
                mma8(c[nt], ah0, ah1, ah2, ah3, b0l, b1l);
            }
        }
    }

    // epilogue
    const float* bsum = bs ? g_bsum2 : g_bsum1;
    int r0 = brow + wr + g;
    int r1 = r0 + 8;
#pragma unroll
    for (int nt = 0; nt < NT; ++nt) {
        int col = nt * 8 + 2 * t;
        if (r0 < M) {
            float v0 = c[nt][0], v1 = c[nt][1];
            if (MODE == 1) { v0 += bias_ext[col]; v1 += bias_ext[col + 1]; }
            if (MODE == 2) {
                v0 = leakyf(v0 + g_B[(size_t)r0 * 128 + col] + bsum[col]);
                v1 = leakyf(v1 + g_B[(size_t)r0 * 128 + col + 1] + bsum[col + 1]);
            }
            *(float2*)&C[(size_t)r0 * KOUT + col] = make_float2(v0, v1);
        }
        if (r1 < M) {
            float v2 = c[nt][2], v3 = c[nt][3];
            if (MODE == 1) { v2 += bias_ext[col]; v3 += bias_ext[col + 1]; }
            if (MODE == 2) {
                v2 = leakyf(v2 + g_B[(size_t)r1 * 128 + col] + bsum[col]);
                v3 = leakyf(v3 + g_B[(size_t)r1 * 128 + col + 1] + bsum[col + 1]);
            }
            *(float2*)&C[(size_t)r1 * KOUT + col] = make_float2(v2, v3);
        }
    }
}

// ---------------- launch ----------------
extern "C" void kernel_launch(void* const* d_in, const int* in_sizes, int n_in,
                              void* d_out, int out_size) {
    const float* X     = (const float*)d_in[0];
    const int* eidx    = (const int*)d_in[1];
    const int* hidx    = (const int*)d_in[2];
    const float* hc1w  = (const float*)d_in[3];
    const float* hc1b  = (const float*)d_in[4];
    const float* lin1w = (const float*)d_in[5];
    const float* lin1b = (const float*)d_in[6];
    const float* hc2w  = (const float*)d_in[7];
    const float* hc2b  = (const float*)d_in[8];
    const float* lin2w = (const float*)d_in[9];
    const float* lin2b = (const float*)d_in[10];
    const float* c1wrel  = (const float*)d_in[11];
    const float* c1brel  = (const float*)d_in[12];
    const float* c1wroot = (const float*)d_in[13];
    const float* glin1w  = (const float*)d_in[14];
    const float* glin1b  = (const float*)d_in[15];
    const float* c2wrel  = (const float*)d_in[16];
    const float* c2brel  = (const float*)d_in[17];
    const float* c2wroot = (const float*)d_in[18];
    const float* glin2w  = (const float*)d_in[19];
    const float* glin2b  = (const float*)d_in[20];
    const float* fcw = (const float*)d_in[21];
    const float* fcb = (const float*)d_in[22];

    const size_t NX = (size_t)NN * HID;
    const size_t NYsz = (size_t)NN * OUTC;
    bool full_out = ((size_t)out_size >= NX + NYsz);
    float* outX = (float*)d_out;
    float* outY = full_out ? (outX + NX) : (float*)d_out;
    int final_csel = full_out ? -1 : 3;
    int fc_asel    = full_out ? -1 : 3;
    const float* fc_Aext = full_out ? outX : (const float*)0;

    const int TPB = 256;
    const int SMEMSZ = 128 * 68 * 4 + 4096 * 16;    // 34816 + 65536 = 100352 B
    int gG = (NN + 127) / 128;
    int gbE   = (NE + TPB - 1) / TPB;
    int gbHEw = (NHE * 32 + TPB - 1) / TPB;
    int gbNw  = (NN * 32 + TPB - 1) / TPB;

    cudaFuncSetAttribute((const void*)gemm_tf32<0, 16>, cudaFuncAttributeMaxDynamicSharedMemorySize, SMEMSZ);
    cudaFuncSetAttribute((const void*)gemm_tf32<2, 16>, cudaFuncAttributeMaxDynamicSharedMemorySize, SMEMSZ);
    cudaFuncSetAttribute((const void*)gemm_tf32<1, 8>,  cudaFuncAttributeMaxDynamicSharedMemorySize, SMEMSZ);

    // ---- weight prep (independent of CSR) ----
    WList wl;
    wl.a[0] = hc1w;    wl.b[0] = 0;      wl.ncols[0] = 128;
    wl.a[1] = lin1w;   wl.b[1] = 0;      wl.ncols[1] = 128;
    wl.a[2] = hc2w;    wl.b[2] = 0;      wl.ncols[2] = 128;
    wl.a[3] = lin2w;   wl.b[3] = 0;      wl.ncols[3] = 128;
    wl.a[4] = c1wrel;  wl.b[4] = 0;      wl.ncols[4] = 128;
    wl.a[5] = c1wroot; wl.b[5] = glin1w; wl.ncols[5] = 128;
    wl.a[6] = c2wrel;  wl.b[6] = 0;      wl.ncols[6] = 128;
    wl.a[7] = c2wroot; wl.b[7] = glin2w; wl.ncols[7] = 128;
    wl.a[8] = fcw;     wl.b[8] = 0;      wl.ncols[8] = 64;
    decompose_kernel<<<dim3(32, 9), TPB>>>(wl);
    bias_combine_kernel<<<1, 128>>>(c1brel, glin1b, c2brel, glin2b);

    // ---- dtype detect + CSR build ----
    detect_kernel<<<1, 256>>>(hidx);
    zero_deg_kernel<<<(NN + TPB - 1) / TPB, TPB>>>();
    count_kernel<<<gbE, TPB>>>(hidx, eidx);
    scan_kernel<<<3, 1024>>>();
    fill_kernel<<<gbE, TPB>>>(hidx, eidx);

    // ---- layer 1 (hypergraph) ----
    gemm_tf32<0, 16><<<gG, TPB, SMEMSZ>>>(X, 0, 0, -1, 0, 0, 0, NN);   // g_A = X @ hc1w
    gemm_tf32<0, 16><<<gG, TPB, SMEMSZ>>>(X, 0, 0, -1, 1, 1, 0, NN);   // g_B = X @ lin1w
    gather_he_kernel<<<gbHEw, TPB>>>();
    gather_node_fuse_kernel<<<gbNw, TPB>>>((const float4*)hc1b, (const float4*)lin1b, 2);

    // ---- layer 2 (hypergraph) ----
    gemm_tf32<0, 16><<<gG, TPB, SMEMSZ>>>(0, 0, 0, 2, 0, 2, 0, NN);    // g_A = g_X1 @ hc2w
    gemm_tf32<0, 16><<<gG, TPB, SMEMSZ>>>(0, 0, 0, 2, 1, 3, 0, NN);    // g_B = g_X1 @ lin2w
    gather_he_kernel<<<gbHEw, TPB>>>();
    gather_node_fuse_kernel<<<gbNw, TPB>>>((const float4*)hc2b, (const float4*)lin2b, 3);

    // ---- layer 3 (graph) ----
    gather_edge_kernel<<<gbNw, TPB>>>(3);                              // g_A = segsum(g_X2)
    gemm_tf32<0, 16><<<gG, TPB, SMEMSZ>>>(0, 0, 0, 0, 1, 4, 0, NN);    // g_B = g_A @ c1wrel
    gemm_tf32<2, 16><<<gG, TPB, SMEMSZ>>>(0, 0, 0, 3, 2, 5, 0, NN);    // g_X1 = leaky(g_X2@Wc1 + g_B + bsum1)

    // ---- layer 4 (graph) ----
    gather_edge_kernel<<<gbNw, TPB>>>(2);                              // g_A = segsum(g_X1)
    gemm_tf32<0, 16><<<gG, TPB, SMEMSZ>>>(0, 0, 0, 0, 1, 6, 0, NN);    // g_B = g_A @ c2wrel
    gemm_tf32<2, 16><<<gG, TPB, SMEMSZ>>>(0, outX, 0, 2, final_csel, 7, 1, NN);  // X4

    // ---- fc head ----
    gemm_tf32<1, 8><<<gG, TPB, SMEMSZ>>>(fc_Aext, outY, fcb, fc_asel, -1, 8, 0, NN);
}